// round 5
// baseline (speedup 1.0000x reference)
#include <cuda_runtime.h>

// GRU fused recurrence, fp32 SIMT + packed f32x2 FMA (sm_103a).
// grid = 512 CTAs x 8 batch rows; block = 160 threads, thread = column k (<150).
// Weights hoisted to registers ONCE (no in-loop LDG), pre-packed into f32x2
// feature-pairs. Activations staged in SMEM [r][f], read as broadcast LDS.128
// reinterpreted as two packed f32x2 operands (no packing instructions).
// Accumulators are packed over even/odd features; lanes summed at gate time.

#define TT   128
#define FF   64
#define NU   50
#define K3   150
#define BR   8
#define NTHR 160
#define HP   52   // h row pitch (floats), 16B-aligned rows

typedef unsigned long long u64;

__device__ __forceinline__ void fma2(u64& d, u64 a, u64 b, u64 c) {
    asm("fma.rn.f32x2 %0, %1, %2, %3;" : "=l"(d) : "l"(a), "l"(b), "l"(c));
}
__device__ __forceinline__ u64 pack2(float lo, float hi) {
    u64 r;
    asm("mov.b64 %0, {%1, %2};" : "=l"(r) : "f"(lo), "f"(hi));
    return r;
}
__device__ __forceinline__ float2 unpack2(u64 v) {
    float2 r;
    asm("mov.b64 {%0, %1}, %2;" : "=f"(r.x), "=f"(r.y) : "l"(v));
    return r;
}
__device__ __forceinline__ float sigmoidf_(float v) {
    return __fdividef(1.0f, 1.0f + __expf(-v));
}

__global__ __launch_bounds__(NTHR, 2) void gru_fused_kernel(
    const float* __restrict__ x,    // [4096,128,64]
    const float* __restrict__ W,    // [64,150]
    const float* __restrict__ U,    // [50,150]
    const float* __restrict__ bvec, // [2,150]
    const float* __restrict__ Wd,   // [50,1]
    const float* __restrict__ bd,   // [1]
    float* __restrict__ out)        // [4096,1]
{
    __shared__ __align__(16) float sx[BR * FF];  // [r][f], pitch 64
    __shared__ __align__(16) float sh[BR * HP];  // [r][j], pitch 52
    __shared__ float sgr[BR * NU];               // r-gate exchange
    __shared__ float shc[BR * NU];               // hcand exchange

    const int tid  = threadIdx.x;
    const int k    = tid;
    const int brow = blockIdx.x * BR;

    for (int i = tid; i < BR * HP; i += NTHR) sh[i] = 0.0f;

    float b0k = 0.0f, b1k = 0.0f;
    // Weights for this thread's column, packed as f32x2 feature-pairs.
    u64 wp[FF / 2];   // 32 pairs
    u64 up[NU / 2];   // 25 pairs
    if (k < K3) {
        b0k = __ldg(&bvec[k]);
        b1k = __ldg(&bvec[K3 + k]);
        #pragma unroll
        for (int fg = 0; fg < FF / 2; fg++)
            wp[fg] = pack2(__ldg(&W[(2 * fg) * K3 + k]),
                           __ldg(&W[(2 * fg + 1) * K3 + k]));
        #pragma unroll
        for (int jg = 0; jg < NU / 2; jg++)
            up[jg] = pack2(__ldg(&U[(2 * jg) * K3 + k]),
                           __ldg(&U[(2 * jg + 1) * K3 + k]));
    }

    // prefetch x tile for t = 0 (BR*FF = 512 elems, 160 threads -> <=4 each)
    float xr[4];
    #pragma unroll
    for (int i = 0; i < 4; i++) {
        int idx = tid + i * NTHR;
        if (idx < BR * FF) {
            int r = idx >> 6, f = idx & 63;
            xr[i] = __ldg(&x[(size_t)(brow + r) * (TT * FF) + f]);
        }
    }
    __syncthreads();  // h init visible

    #pragma unroll 1
    for (int t = 0; t < TT; t++) {
        // commit prefetched x tile
        #pragma unroll
        for (int i = 0; i < 4; i++) {
            int idx = tid + i * NTHR;
            if (idx < BR * FF) sx[idx] = xr[i];
        }
        __syncthreads();  // (a) sx ready; prev step's h writes ordered

        // prefetch next step
        if (t + 1 < TT) {
            #pragma unroll
            for (int i = 0; i < 4; i++) {
                int idx = tid + i * NTHR;
                if (idx < BR * FF) {
                    int r = idx >> 6, f = idx & 63;
                    xr[i] = __ldg(&x[(size_t)(brow + r) * (TT * FF)
                                     + (size_t)(t + 1) * FF + f]);
                }
            }
        }

        u64 accX[BR], accH[BR];
        #pragma unroll
        for (int r = 0; r < BR; r++) { accX[r] = 0ull; accH[r] = 0ull; }

        if (k < K3) {
            // xp partial: packed over feature pairs
            #pragma unroll
            for (int fg = 0; fg < FF / 4; fg++) {
                const int f0 = fg * 4;
                #pragma unroll
                for (int r = 0; r < BR; r++) {
                    ulonglong2 xv = *(const ulonglong2*)(sx + r * FF + f0);
                    fma2(accX[r], xv.x, wp[2 * fg],     accX[r]);
                    fma2(accX[r], xv.y, wp[2 * fg + 1], accX[r]);
                }
            }
            // hp partial: 12 quads + 1 tail pair (j = 48,49)
            #pragma unroll
            for (int jg = 0; jg < 12; jg++) {
                const int j0 = jg * 4;
                #pragma unroll
                for (int r = 0; r < BR; r++) {
                    ulonglong2 hv = *(const ulonglong2*)(sh + r * HP + j0);
                    fma2(accH[r], hv.x, up[2 * jg],     accH[r]);
                    fma2(accH[r], hv.y, up[2 * jg + 1], accH[r]);
                }
            }
            #pragma unroll
            for (int r = 0; r < BR; r++) {
                u64 hv = *(const u64*)(sh + r * HP + 48);
                fma2(accH[r], hv, up[24], accH[r]);
            }
        }

        // finalize lane sums + biases
        float aX[BR], aH[BR];
        #pragma unroll
        for (int r = 0; r < BR; r++) {
            float2 px = unpack2(accX[r]);
            float2 ph = unpack2(accH[r]);
            aX[r] = px.x + px.y + b0k;
            aH[r] = ph.x + ph.y + b1k;
        }

        // gates: k in [50,100) -> r; [0,50) -> z; [100,150) -> hcand
        float zv[BR];
        if (k >= NU && k < 2 * NU) {
            const int j = k - NU;
            #pragma unroll
            for (int r = 0; r < BR; r++)
                sgr[r * NU + j] = sigmoidf_(aX[r] + aH[r]);
        }
        if (k < NU) {
            #pragma unroll
            for (int r = 0; r < BR; r++)
                zv[r] = sigmoidf_(aX[r] + aH[r]);
        }
        __syncthreads();  // (b) sgr ready

        if (k >= 2 * NU && k < K3) {
            const int j = k - 2 * NU;
            #pragma unroll
            for (int r = 0; r < BR; r++) {
                float pre = aX[r] + sgr[r * NU + j] * aH[r];
                shc[r * NU + j] = fmaxf(pre, 0.0f);
            }
        }
        __syncthreads();  // (c) shc ready

        if (k < NU) {
            const int j = k;
            #pragma unroll
            for (int r = 0; r < BR; r++) {
                float hold = sh[r * HP + j];
                sh[r * HP + j] = zv[r] * hold + (1.0f - zv[r]) * shc[r * NU + j];
            }
        }
        // next iteration's barrier (a) orders sh writes before reads
    }

    __syncthreads();
    if (tid < BR) {
        float acc = bd[0];
        #pragma unroll
        for (int j = 0; j < NU; j++)
            acc += sh[tid * HP + j] * __ldg(&Wd[j]);
        out[brow + tid] = acc;
    }
}

extern "C" void kernel_launch(void* const* d_in, const int* in_sizes, int n_in,
                              void* d_out, int out_size) {
    (void)in_sizes; (void)n_in; (void)out_size;
    const float* x    = (const float*)d_in[0];
    const float* W    = (const float*)d_in[1];
    const float* U    = (const float*)d_in[2];
    const float* bvec = (const float*)d_in[3];
    const float* Wd   = (const float*)d_in[4];
    const float* bd   = (const float*)d_in[5];
    float* out = (float*)d_out;

    gru_fused_kernel<<<4096 / BR, NTHR>>>(x, W, U, bvec, Wd, bd, out);
}